// round 3
// baseline (speedup 1.0000x reference)
#include <cuda_runtime.h>
#include <cstdint>

#define HH 512
#define WW 512
#define BB 2
#define PP 65536
#define CC 8
#define RR 4
#define HWPIX (HH * WW)
#define NPIX (BB * HWPIX)
#define NPTS (BB * PP)

#define ZNEAR 0.1f
#define ZFAR  10.0f
#define EPS 1e-8f

// Scratch: per-pixel accumulator, 3 x float4 per pixel:
//   [0] = w*feat[0..3], [1] = w*feat[4..7], [2] = {sum_w, sum_w*z, sum_ws, pad}
__device__ float4 g_acc[NPIX * 3];
__device__ int    g_zmin[NPIX + 16];   // +16 pad: 12-wide aligned row windows may read past row end

__device__ __forceinline__ void red_add_v4(float4* addr, float a, float b, float c, float d) {
    asm volatile("red.global.add.v4.f32 [%0], {%1, %2, %3, %4};"
                 :: "l"(addr), "f"(a), "f"(b), "f"(c), "f"(d)
                 : "memory");
}

// NDC coordinate of pixel center q, EXACTLY like reference: 2.0*q/511 - 1.0 (IEEE ops)
__device__ __forceinline__ float pix_ndc(int q) {
    return __fadd_rn(__fdiv_rn(__fmul_rn(2.0f, (float)q), 511.0f), -1.0f);
}

__global__ void init_kernel() {
    int i = blockIdx.x * blockDim.x + threadIdx.x;   // one thread per 4 pixels
    if (i * 4 >= NPIX) return;
    reinterpret_cast<int4*>(g_zmin)[i] =
        make_int4(__float_as_int(ZFAR), __float_as_int(ZFAR),
                  __float_as_int(ZFAR), __float_as_int(ZFAR));
    float4 z4 = make_float4(0.f, 0.f, 0.f, 0.f);
    float4* a = &g_acc[i * 12];
    #pragma unroll
    for (int k = 0; k < 12; ++k) a[k] = z4;
}

__global__ void zmin_kernel(const float* __restrict__ pts,
                            const float* __restrict__ max_radius) {
    __shared__ float s_ndc[512];
    for (int t = threadIdx.x; t < 512; t += blockDim.x)
        s_ndc[t] = pix_ndc(t);
    __syncthreads();

    int i = blockIdx.x * blockDim.x + threadIdx.x;
    if (i >= NPTS) return;
    float x = pts[i * 3 + 0];
    float y = pts[i * 3 + 1];
    float z = pts[i * 3 + 2];
    if (!(z > ZNEAR && z < ZFAR)) return;
    float mr = max_radius[0];
    float r2 = __fmul_rn(mr, mr);

    // pixel center, IEEE order matching reference: ((x+1)*0.5)*511
    float px = __fmul_rn(__fmul_rn(__fadd_rn(x, 1.0f), 0.5f), 511.0f);
    float py = __fmul_rn(__fmul_rn(__fadd_rn(y, 1.0f), 0.5f), 511.0f);
    int cx = (int)rintf(px);
    int cy = (int)rintf(py);
    int zb = __float_as_int(z);
    int base = (i / PP) * HWPIX;

    for (int dy = -RR; dy <= RR; ++dy) {
        int qy = cy + dy;
        if ((unsigned)qy >= (unsigned)HH) continue;
        float ddy = __fsub_rn(s_ndc[qy], y);
        float dy2 = __fmul_rn(ddy, ddy);
        int rowbase = base + qy * WW;
        #pragma unroll
        for (int dx = -RR; dx <= RR; ++dx) {
            int qx = cx + dx;
            if ((unsigned)qx >= (unsigned)WW) continue;
            float ddx = __fsub_rn(s_ndc[qx], x);
            float d2 = __fadd_rn(__fmul_rn(ddx, ddx), dy2);
            if (d2 <= r2) {
                atomicMin(&g_zmin[rowbase + qx], zb);
            }
        }
    }
}

__global__ void splat_kernel(const float* __restrict__ pts,
                             const float* __restrict__ feats,
                             const float* __restrict__ sigmas,
                             const float* __restrict__ max_radius) {
    __shared__ float s_ndc[512];
    for (int t = threadIdx.x; t < 512; t += blockDim.x)
        s_ndc[t] = pix_ndc(t);
    __syncthreads();

    int i = blockIdx.x * blockDim.x + threadIdx.x;
    if (i >= NPTS) return;
    float x = pts[i * 3 + 0];
    float y = pts[i * 3 + 1];
    float z = pts[i * 3 + 2];
    if (!(z > ZNEAR && z < ZFAR)) return;
    float mr = max_radius[0];
    float r2 = __fmul_rn(mr, mr);

    float sg = sigmas[i];
    float inv2s2 = 0.5f / (sg * sg);
    float nz2 = -2.0f * z;   // -(z - zm)/GAMMA = -2z + 2zm

    const float4* fp = reinterpret_cast<const float4*>(feats + (size_t)i * CC);
    float4 f0 = fp[0];
    float4 f1 = fp[1];

    float px = __fmul_rn(__fmul_rn(__fadd_rn(x, 1.0f), 0.5f), 511.0f);
    float py = __fmul_rn(__fmul_rn(__fadd_rn(y, 1.0f), 0.5f), 511.0f);
    int cx = (int)rintf(px);
    int cy = (int)rintf(py);
    int base = (i / PP) * HWPIX;

    // 12-wide aligned candidate window: covers [cx-4, cx+4]; extra candidates
    // are culled by the exact d2<=r2 test (|dx|>=5 always fails the radius).
    int start = cx - RR;
    if (start < 0) start = 0;
    start &= ~3;

    for (int dy = -RR; dy <= RR; ++dy) {
        int qy = cy + dy;
        if ((unsigned)qy >= (unsigned)HH) continue;
        float ddy = __fsub_rn(s_ndc[qy], y);
        float dy2 = __fmul_rn(ddy, ddy);
        int rowbase = base + qy * WW;

        // 3 aligned 128-bit loads cover the whole window
        const int4* zrow = reinterpret_cast<const int4*>(&g_zmin[rowbase + start]);
        int4 zv0 = zrow[0];
        int4 zv1 = zrow[1];
        int4 zv2 = zrow[2];
        int zw[12] = {zv0.x, zv0.y, zv0.z, zv0.w,
                      zv1.x, zv1.y, zv1.z, zv1.w,
                      zv2.x, zv2.y, zv2.z, zv2.w};

        #pragma unroll
        for (int j = 0; j < 12; ++j) {
            int qx = start + j;
            if (qx >= WW) break;
            float ddx = __fsub_rn(s_ndc[qx], x);
            float d2 = __fadd_rn(__fmul_rn(ddx, ddx), dy2);
            if (d2 <= r2) {
                float zm = __int_as_float(zw[j]);
                float ws = __expf(-d2 * inv2s2);
                float w  = ws * __expf(fmaf(2.0f, zm, nz2));
                float4* ap = &g_acc[(rowbase + qx) * 3];
                red_add_v4(ap + 0, w * f0.x, w * f0.y, w * f0.z, w * f0.w);
                red_add_v4(ap + 1, w * f1.x, w * f1.y, w * f1.z, w * f1.w);
                red_add_v4(ap + 2, w, w * z, ws, 0.0f);
            }
        }
    }
}

__global__ void finalize_kernel(float* __restrict__ out) {
    int t = blockIdx.x * blockDim.x + threadIdx.x;   // one thread per 4 pixels
    int i0 = t * 4;
    if (i0 >= NPIX) return;

    float4 depth4, mask4;
    float* dp = &depth4.x;
    float* mp = &mask4.x;
    float4* outc = reinterpret_cast<float4*>(out);

    #pragma unroll
    for (int j = 0; j < 4; ++j) {
        int i = i0 + j;
        float4 a0 = g_acc[i * 3 + 0];
        float4 a1 = g_acc[i * 3 + 1];
        float4 a2 = g_acc[i * 3 + 2];
        float inv = 1.0f / (a2.x + EPS);
        outc[i * 2 + 0] = make_float4(a0.x * inv, a0.y * inv, a0.z * inv, a0.w * inv);
        outc[i * 2 + 1] = make_float4(a1.x * inv, a1.y * inv, a1.z * inv, a1.w * inv);
        dp[j] = a2.y * inv;
        mp[j] = 1.0f - __expf(-a2.z);
    }

    reinterpret_cast<float4*>(out + (size_t)NPIX * CC)[t] = depth4;
    reinterpret_cast<float4*>(out + (size_t)NPIX * CC + NPIX)[t] = mask4;
}

extern "C" void kernel_launch(void* const* d_in, const int* in_sizes, int n_in,
                              void* d_out, int out_size) {
    const float* pts        = (const float*)d_in[0];  // [B,P,3]
    const float* feats      = (const float*)d_in[1];  // [B,P,8]
    const float* sigmas     = (const float*)d_in[2];  // [B,P]
    const float* max_radius = (const float*)d_in[3];  // scalar
    float* out = (float*)d_out;

    {
        int threads = 256;
        int blocks = (NPIX / 4 + threads - 1) / threads;
        init_kernel<<<blocks, threads>>>();
    }
    {
        int threads = 256;
        int blocks = (NPTS + threads - 1) / threads;
        zmin_kernel<<<blocks, threads>>>(pts, max_radius);
        splat_kernel<<<blocks, threads>>>(pts, feats, sigmas, max_radius);
    }
    {
        int threads = 256;
        int blocks = (NPIX / 4 + threads - 1) / threads;
        finalize_kernel<<<blocks, threads>>>(out);
    }
}

// round 4
// speedup vs baseline: 1.0149x; 1.0149x over previous
#include <cuda_runtime.h>
#include <cstdint>

#define HH 512
#define WW 512
#define BB 2
#define PP 65536
#define CC 8
#define RR 4
#define HWPIX (HH * WW)
#define NPIX (BB * HWPIX)
#define NPTS (BB * PP)

#define ZNEAR 0.1f
#define ZFAR  10.0f
#define EPS 1e-8f

// Scratch: per-pixel accumulator, 3 x float4 per pixel:
//   [0] = w*feat[0..3], [1] = w*feat[4..7], [2] = {sum_w, sum_w*z, sum_ws, pad}
__device__ float4 g_acc[NPIX * 3];
__device__ int    g_zmin[NPIX + 16];   // +16 pad: 12-wide aligned row windows may read past row end

__device__ __forceinline__ void red_add_v4(float4* addr, float a, float b, float c, float d) {
    asm volatile("red.global.add.v4.f32 [%0], {%1, %2, %3, %4};"
                 :: "l"(addr), "f"(a), "f"(b), "f"(c), "f"(d)
                 : "memory");
}

// NDC coordinate of pixel center q, EXACTLY like reference: 2.0*q/511 - 1.0 (IEEE ops)
__device__ __forceinline__ float pix_ndc(int q) {
    return __fadd_rn(__fdiv_rn(__fmul_rn(2.0f, (float)q), 511.0f), -1.0f);
}

__global__ void init_kernel() {
    int i = blockIdx.x * blockDim.x + threadIdx.x;   // one thread per 4 pixels
    if (i * 4 >= NPIX) return;
    reinterpret_cast<int4*>(g_zmin)[i] =
        make_int4(__float_as_int(ZFAR), __float_as_int(ZFAR),
                  __float_as_int(ZFAR), __float_as_int(ZFAR));
    float4 z4 = make_float4(0.f, 0.f, 0.f, 0.f);
    float4* a = &g_acc[i * 12];
    #pragma unroll
    for (int k = 0; k < 12; ++k) a[k] = z4;
}

__global__ void zmin_kernel(const float* __restrict__ pts,
                            const float* __restrict__ max_radius) {
    __shared__ float s_ndc[512];
    for (int t = threadIdx.x; t < 512; t += blockDim.x)
        s_ndc[t] = pix_ndc(t);
    __syncthreads();

    int i = blockIdx.x * blockDim.x + threadIdx.x;
    if (i >= NPTS) return;
    float x = pts[i * 3 + 0];
    float y = pts[i * 3 + 1];
    float z = pts[i * 3 + 2];
    if (!(z > ZNEAR && z < ZFAR)) return;
    float mr = max_radius[0];
    float r2 = __fmul_rn(mr, mr);

    // pixel center, IEEE order matching reference: ((x+1)*0.5)*511
    float px = __fmul_rn(__fmul_rn(__fadd_rn(x, 1.0f), 0.5f), 511.0f);
    float py = __fmul_rn(__fmul_rn(__fadd_rn(y, 1.0f), 0.5f), 511.0f);
    int cx = (int)rintf(px);
    int cy = (int)rintf(py);
    int zb = __float_as_int(z);
    int base = (i / PP) * HWPIX;

    for (int dy = -RR; dy <= RR; ++dy) {
        int qy = cy + dy;
        if ((unsigned)qy >= (unsigned)HH) continue;
        float ddy = __fsub_rn(s_ndc[qy], y);
        float dy2 = __fmul_rn(ddy, ddy);
        int rowbase = base + qy * WW;
        #pragma unroll
        for (int dx = -RR; dx <= RR; ++dx) {
            int qx = cx + dx;
            if ((unsigned)qx >= (unsigned)WW) continue;
            float ddx = __fsub_rn(s_ndc[qx], x);
            float d2 = __fadd_rn(__fmul_rn(ddx, ddx), dy2);
            if (d2 <= r2) {
                atomicMin(&g_zmin[rowbase + qx], zb);
            }
        }
    }
}

__global__ void splat_kernel(const float* __restrict__ pts,
                             const float* __restrict__ feats,
                             const float* __restrict__ sigmas,
                             const float* __restrict__ max_radius) {
    __shared__ float s_ndc[512];
    for (int t = threadIdx.x; t < 512; t += blockDim.x)
        s_ndc[t] = pix_ndc(t);
    __syncthreads();

    int i = blockIdx.x * blockDim.x + threadIdx.x;
    if (i >= NPTS) return;
    float x = pts[i * 3 + 0];
    float y = pts[i * 3 + 1];
    float z = pts[i * 3 + 2];
    if (!(z > ZNEAR && z < ZFAR)) return;
    float mr = max_radius[0];
    float r2 = __fmul_rn(mr, mr);

    float sg = sigmas[i];
    float inv2s2 = 0.5f / (sg * sg);
    float nz2 = -2.0f * z;   // -(z - zm)/GAMMA = -2z + 2zm

    const float4* fp = reinterpret_cast<const float4*>(feats + (size_t)i * CC);
    float4 f0 = fp[0];
    float4 f1 = fp[1];

    float px = __fmul_rn(__fmul_rn(__fadd_rn(x, 1.0f), 0.5f), 511.0f);
    float py = __fmul_rn(__fmul_rn(__fadd_rn(y, 1.0f), 0.5f), 511.0f);
    int cx = (int)rintf(px);
    int cy = (int)rintf(py);
    int base = (i / PP) * HWPIX;

    // 12-wide aligned candidate window: covers [cx-4, cx+4]; extra candidates
    // are culled by the exact d2<=r2 test (|dx|>=5 always fails the radius).
    int start = cx - RR;
    if (start < 0) start = 0;
    start &= ~3;

    for (int dy = -RR; dy <= RR; ++dy) {
        int qy = cy + dy;
        if ((unsigned)qy >= (unsigned)HH) continue;
        float ddy = __fsub_rn(s_ndc[qy], y);
        float dy2 = __fmul_rn(ddy, ddy);
        int rowbase = base + qy * WW;

        // 3 aligned 128-bit loads cover the whole window
        const int4* zrow = reinterpret_cast<const int4*>(&g_zmin[rowbase + start]);
        int4 zv0 = zrow[0];
        int4 zv1 = zrow[1];
        int4 zv2 = zrow[2];
        int zw[12] = {zv0.x, zv0.y, zv0.z, zv0.w,
                      zv1.x, zv1.y, zv1.z, zv1.w,
                      zv2.x, zv2.y, zv2.z, zv2.w};

        #pragma unroll
        for (int j = 0; j < 12; ++j) {
            int qx = start + j;
            if (qx >= WW) break;
            float ddx = __fsub_rn(s_ndc[qx], x);
            float d2 = __fadd_rn(__fmul_rn(ddx, ddx), dy2);
            if (d2 <= r2) {
                float zm = __int_as_float(zw[j]);
                float ws = __expf(-d2 * inv2s2);
                float w  = ws * __expf(fmaf(2.0f, zm, nz2));
                float4* ap = &g_acc[(rowbase + qx) * 3];
                red_add_v4(ap + 0, w * f0.x, w * f0.y, w * f0.z, w * f0.w);
                red_add_v4(ap + 1, w * f1.x, w * f1.y, w * f1.z, w * f1.w);
                red_add_v4(ap + 2, w, w * z, ws, 0.0f);
            }
        }
    }
}

__global__ void finalize_kernel(float* __restrict__ out) {
    int t = blockIdx.x * blockDim.x + threadIdx.x;   // one thread per 4 pixels
    int i0 = t * 4;
    if (i0 >= NPIX) return;

    float4 depth4, mask4;
    float* dp = &depth4.x;
    float* mp = &mask4.x;
    float4* outc = reinterpret_cast<float4*>(out);

    #pragma unroll
    for (int j = 0; j < 4; ++j) {
        int i = i0 + j;
        float4 a0 = g_acc[i * 3 + 0];
        float4 a1 = g_acc[i * 3 + 1];
        float4 a2 = g_acc[i * 3 + 2];
        float inv = 1.0f / (a2.x + EPS);
        outc[i * 2 + 0] = make_float4(a0.x * inv, a0.y * inv, a0.z * inv, a0.w * inv);
        outc[i * 2 + 1] = make_float4(a1.x * inv, a1.y * inv, a1.z * inv, a1.w * inv);
        dp[j] = a2.y * inv;
        mp[j] = 1.0f - __expf(-a2.z);
    }

    reinterpret_cast<float4*>(out + (size_t)NPIX * CC)[t] = depth4;
    reinterpret_cast<float4*>(out + (size_t)NPIX * CC + NPIX)[t] = mask4;
}

extern "C" void kernel_launch(void* const* d_in, const int* in_sizes, int n_in,
                              void* d_out, int out_size) {
    const float* pts        = (const float*)d_in[0];  // [B,P,3]
    const float* feats      = (const float*)d_in[1];  // [B,P,8]
    const float* sigmas     = (const float*)d_in[2];  // [B,P]
    const float* max_radius = (const float*)d_in[3];  // scalar
    float* out = (float*)d_out;

    {
        int threads = 256;
        int blocks = (NPIX / 4 + threads - 1) / threads;
        init_kernel<<<blocks, threads>>>();
    }
    {
        int threads = 256;
        int blocks = (NPTS + threads - 1) / threads;
        zmin_kernel<<<blocks, threads>>>(pts, max_radius);
        splat_kernel<<<blocks, threads>>>(pts, feats, sigmas, max_radius);
    }
    {
        int threads = 256;
        int blocks = (NPIX / 4 + threads - 1) / threads;
        finalize_kernel<<<blocks, threads>>>(out);
    }
}